// round 5
// baseline (speedup 1.0000x reference)
#include <cuda_runtime.h>
#include <cstdint>
#include <cstddef>

// ---------------------------------------------------------------------------
// Scalarizer fused kernel (fp32 exact, FFMA2 / f32x2 packed math)
//
// Per row n (131072 rows):
//   v_red[3][128]  = v[n] (3x512) @ W_dimred^T (512x128)
//   norm[k]        = ||v_red[:,k]||  (over the 3-axis)
//   dir[i][e]      = sum_r v_red[i][r] * W_emb[e][r]        (3x3)
//   ndir[i][e]     = dir[i][e] / (||dir[:,e]|| + 1e-3)
//   nvred[i][k]    = v_red[i][k] / (norm[k] + 1e-3)
//   proj[e][k]     = sum_i nvred[i][k] * ndir[i][e]
//   v2[512]        = [norm, proj.flatten()]
//   h = v2 @ W_lin^T + b_lin ; LayerNorm(gamma,beta,eps=1e-5) ; exact GELU
// ---------------------------------------------------------------------------

#define ULL unsigned long long

// Transposed weight scratch (device globals: allocation-free contract)
static __device__ float g_WdT[512 * 128];   // [k][r]  (k=hidden, r=reduced)
static __device__ float g_WlT[512 * 512];   // [c][o]  (c=4*reduced, o=out)

__device__ __forceinline__ ULL f2u(float x, float y) {
    ULL r; asm("mov.b64 %0, {%1, %2};" : "=l"(r) : "f"(x), "f"(y)); return r;
}
__device__ __forceinline__ ULL fdup(float x) {
    ULL r; asm("mov.b64 %0, {%1, %1};" : "=l"(r) : "f"(x)); return r;
}
__device__ __forceinline__ ULL ffma2(ULL a, ULL b, ULL c) {
    ULL d; asm("fma.rn.f32x2 %0, %1, %2, %3;" : "=l"(d) : "l"(a), "l"(b), "l"(c)); return d;
}
__device__ __forceinline__ float2 u2f(ULL v) {
    float2 f; asm("mov.b64 {%0, %1}, %2;" : "=f"(f.x), "=f"(f.y) : "l"(v)); return f;
}

// --------------------------- prep: weight transpose -------------------------
__global__ void prep_transpose_kernel(const float* __restrict__ Wd,
                                      const float* __restrict__ Wl) {
    int i = blockIdx.x * blockDim.x + threadIdx.x;
    if (i < 512 * 128) {            // WdT[k*128 + r] = Wd[r*512 + k]
        int k = i >> 7, r = i & 127;
        g_WdT[i] = Wd[r * 512 + k];
    }
    if (i < 512 * 512) {            // WlT[c*512 + o] = Wl[o*512 + c]
        int c = i >> 9, o = i & 511;
        g_WlT[i] = Wl[o * 512 + c];
    }
}

// ------------------------------- main kernel --------------------------------
// 256 threads, 32 rows per block, dynamic smem layout (floats):
//   [0, 16384)      : tile region (phase1: sA 96x68 + sB 64x128 ; phase3: sB2 32x512)
//   [16384, 28672)  : sVred 96x128
//   [28672, 45184)  : sV2   32x516 (pitch 516)
//   [45184, 45568)  : sWemb 3x128
static constexpr int SMEM_FLOATS = 45568;

__global__ void __launch_bounds__(256, 1)
scalarizer_kernel(const float* __restrict__ v,
                  const float* __restrict__ W_emb,
                  const float* __restrict__ b_lin,
                  const float* __restrict__ gamma,
                  const float* __restrict__ beta,
                  float* __restrict__ out) {
    extern __shared__ float sm[];
    float* sA    = sm;                 // 96 x 68
    float* sB    = sm + 6528;          // 64 x 128
    float* sB2   = sm;                 // 32 x 512 (reuses tile region)
    float* sVred = sm + 16384;         // 96 x 128
    float* sV2   = sm + 28672;         // 32 x 516
    float* sWemb = sm + 45184;         // 3 x 128

    const int tid  = threadIdx.x;
    const int lane = tid & 31;
    const int warp = tid >> 5;
    const float* slab = v + (size_t)blockIdx.x * (32 * 3 * 512);  // [96][512] contiguous

    // preload W_emb into smem
    for (int i = tid; i < 384; i += 256) sWemb[i] = W_emb[i];

    // ===================== Phase 1: GEMM1 (96x512)@(512x128) =====================
    // thread (tm1, tn1): rows m0..m0+5, cols = tn1*2 + g*32 + {0,1}, g=0..3
    const int tm1 = tid >> 4;       // 0..15
    const int tn1 = tid & 15;       // 0..15
    const int m0  = tm1 * 6;

    ULL acc1[6][4];
#pragma unroll
    for (int j = 0; j < 6; j++)
#pragma unroll
        for (int g = 0; g < 4; g++) acc1[j][g] = 0ull;

    for (int kk = 0; kk < 512; kk += 64) {
        __syncthreads();
        // load A tile: 96 x 64 (float4, pitch 68)
        for (int idx = tid; idx < 96 * 16; idx += 256) {
            int m = idx >> 4, k4 = idx & 15;
            float4 q = *(const float4*)(slab + m * 512 + kk + k4 * 4);
            *(float4*)(sA + m * 68 + k4 * 4) = q;
        }
        // load B tile: 64 x 128 (float4, pitch 128)
        for (int idx = tid; idx < 64 * 32; idx += 256) {
            int k = idx >> 5, n4 = idx & 31;
            *(float4*)(sB + k * 128 + n4 * 4) =
                *(const float4*)(g_WdT + (kk + k) * 128 + n4 * 4);
        }
        __syncthreads();

#pragma unroll 4
        for (int k = 0; k < 64; k++) {
            ULL a2[6];
#pragma unroll
            for (int j = 0; j < 6; j++) a2[j] = fdup(sA[(m0 + j) * 68 + k]);
#pragma unroll
            for (int g = 0; g < 4; g++) {
                float2 bb = *(const float2*)(sB + k * 128 + g * 32 + tn1 * 2);
                ULL b2 = f2u(bb.x, bb.y);
#pragma unroll
                for (int j = 0; j < 6; j++) acc1[j][g] = ffma2(a2[j], b2, acc1[j][g]);
            }
        }
    }

    // write v_red to smem: sVred[m][col], pitch 128
#pragma unroll
    for (int j = 0; j < 6; j++)
#pragma unroll
        for (int g = 0; g < 4; g++) {
            float2 r = u2f(acc1[j][g]);
            *(float2*)(sVred + (m0 + j) * 128 + g * 32 + tn1 * 2) = r;
        }
    __syncthreads();

    // ===================== Phase 2: norms / directions / projections ============
    {
        float weA[3][4];
#pragma unroll
        for (int e = 0; e < 3; e++) {
            float4 q = *(const float4*)(sWemb + e * 128 + lane * 4);
            weA[e][0] = q.x; weA[e][1] = q.y; weA[e][2] = q.z; weA[e][3] = q.w;
        }
        for (int r = warp; r < 32; r += 8) {   // one warp per row
            float vrA[3][4];
#pragma unroll
            for (int i = 0; i < 3; i++) {
                float4 q = *(const float4*)(sVred + (3 * r + i) * 128 + lane * 4);
                vrA[i][0] = q.x; vrA[i][1] = q.y; vrA[i][2] = q.z; vrA[i][3] = q.w;
            }
            // dir[i][e] = sum_k v_red[i][k] * W_emb[e][k]  (warp reduce, all lanes get it)
            float p[3][3];
#pragma unroll
            for (int i = 0; i < 3; i++)
#pragma unroll
                for (int e = 0; e < 3; e++) {
                    float s = vrA[i][0] * weA[e][0] + vrA[i][1] * weA[e][1]
                            + vrA[i][2] * weA[e][2] + vrA[i][3] * weA[e][3];
                    for (int off = 16; off; off >>= 1)
                        s += __shfl_xor_sync(0xffffffffu, s, off);
                    p[i][e] = s;
                }
            float nd[3][3];
#pragma unroll
            for (int e = 0; e < 3; e++) {
                float dn = sqrtf(p[0][e] * p[0][e] + p[1][e] * p[1][e] + p[2][e] * p[2][e]);
                float inv = 1.0f / (dn + 1e-3f);
                nd[0][e] = p[0][e] * inv;
                nd[1][e] = p[1][e] * inv;
                nd[2][e] = p[2][e] * inv;
            }
            float nrmA[4], prA[3][4];
#pragma unroll
            for (int c = 0; c < 4; c++) {
                float v0 = vrA[0][c], v1 = vrA[1][c], v2c = vrA[2][c];
                float nn = sqrtf(v0 * v0 + v1 * v1 + v2c * v2c);
                nrmA[c] = nn;
                float inv = 1.0f / (nn + 1e-3f);
                float nv0 = v0 * inv, nv1 = v1 * inv, nv2 = v2c * inv;
#pragma unroll
                for (int e = 0; e < 3; e++)
                    prA[e][c] = nv0 * nd[0][e] + nv1 * nd[1][e] + nv2 * nd[2][e];
            }
            *(float4*)(sV2 + r * 516 + lane * 4) =
                make_float4(nrmA[0], nrmA[1], nrmA[2], nrmA[3]);
#pragma unroll
            for (int e = 0; e < 3; e++)
                *(float4*)(sV2 + r * 516 + 128 + e * 128 + lane * 4) =
                    make_float4(prA[e][0], prA[e][1], prA[e][2], prA[e][3]);
        }
    }

    // ===================== Phase 3: GEMM2 (32x512)@(512x512) + LN + GELU =========
    // thread (tm3, tn3): rows r0..r0+3, cols = tn3*4 + g*128 + {0..3}, g=0..3
    const int tm3 = tid >> 5;   // 0..7
    const int tn3 = tid & 31;   // 0..31
    const int r0  = tm3 * 4;

    ULL acc3[4][8];
#pragma unroll
    for (int j = 0; j < 4; j++)
#pragma unroll
        for (int q = 0; q < 8; q++) acc3[j][q] = 0ull;

    for (int kk = 0; kk < 512; kk += 32) {
        __syncthreads();
        // load B tile: 32 x 512 from g_WlT (float4)
        for (int idx = tid; idx < 32 * 128; idx += 256) {
            int k = idx >> 7, n4 = idx & 127;
            *(float4*)(sB2 + k * 512 + n4 * 4) =
                *(const float4*)(g_WlT + (size_t)(kk + k) * 512 + n4 * 4);
        }
        __syncthreads();

#pragma unroll 4
        for (int k = 0; k < 32; k++) {
            ULL a2[4];
#pragma unroll
            for (int j = 0; j < 4; j++) a2[j] = fdup(sV2[(r0 + j) * 516 + kk + k]);
#pragma unroll
            for (int g = 0; g < 4; g++) {
                float4 q = *(const float4*)(sB2 + k * 512 + g * 128 + tn3 * 4);
                ULL b0 = f2u(q.x, q.y);
                ULL b1 = f2u(q.z, q.w);
#pragma unroll
                for (int j = 0; j < 4; j++) {
                    acc3[j][g * 2 + 0] = ffma2(a2[j], b0, acc3[j][g * 2 + 0]);
                    acc3[j][g * 2 + 1] = ffma2(a2[j], b1, acc3[j][g * 2 + 1]);
                }
            }
        }
    }

    // epilogue: bias + LayerNorm + exact GELU
    float x[4][16];
#pragma unroll
    for (int j = 0; j < 4; j++)
#pragma unroll
        for (int g = 0; g < 4; g++) {
            float2 lo = u2f(acc3[j][g * 2 + 0]);
            float2 hi = u2f(acc3[j][g * 2 + 1]);
            x[j][g * 4 + 0] = lo.x; x[j][g * 4 + 1] = lo.y;
            x[j][g * 4 + 2] = hi.x; x[j][g * 4 + 3] = hi.y;
        }

    float bias[16], gam[16], bet[16];
#pragma unroll
    for (int g = 0; g < 4; g++) {
        float4 qb = *(const float4*)(b_lin + g * 128 + tn3 * 4);
        float4 qg = *(const float4*)(gamma + g * 128 + tn3 * 4);
        float4 qe = *(const float4*)(beta  + g * 128 + tn3 * 4);
        bias[g*4+0]=qb.x; bias[g*4+1]=qb.y; bias[g*4+2]=qb.z; bias[g*4+3]=qb.w;
        gam [g*4+0]=qg.x; gam [g*4+1]=qg.y; gam [g*4+2]=qg.z; gam [g*4+3]=qg.w;
        bet [g*4+0]=qe.x; bet [g*4+1]=qe.y; bet [g*4+2]=qe.z; bet [g*4+3]=qe.w;
    }

#pragma unroll
    for (int j = 0; j < 4; j++) {
        float s = 0.0f, ss = 0.0f;
#pragma unroll
        for (int c = 0; c < 16; c++) {
            x[j][c] += bias[c];
            s  += x[j][c];
            ss += x[j][c] * x[j][c];
        }
        for (int off = 16; off; off >>= 1) {
            s  += __shfl_xor_sync(0xffffffffu, s,  off);
            ss += __shfl_xor_sync(0xffffffffu, ss, off);
        }
        float mu   = s * (1.0f / 512.0f);
        float var  = ss * (1.0f / 512.0f) - mu * mu;
        float rstd = rsqrtf(var + 1e-5f);

        size_t rowbase = ((size_t)blockIdx.x * 32 + r0 + j) * 512;
#pragma unroll
        for (int g = 0; g < 4; g++) {
            float o[4];
#pragma unroll
            for (int c = 0; c < 4; c++) {
                int idx = g * 4 + c;
                float y = (x[j][idx] - mu) * rstd * gam[idx] + bet[idx];
                o[c] = 0.5f * y * (1.0f + erff(y * 0.70710678118654752f));
            }
            *(float4*)(out + rowbase + g * 128 + tn3 * 4) =
                make_float4(o[0], o[1], o[2], o[3]);
        }
    }
}

// ------------------------------- launch --------------------------------------
extern "C" void kernel_launch(void* const* d_in, const int* in_sizes, int n_in,
                              void* d_out, int out_size) {
    (void)in_sizes; (void)n_in; (void)out_size;
    const float* v  = (const float*)d_in[0];
    const float* Wd = (const float*)d_in[1];
    const float* We = (const float*)d_in[2];
    const float* Wl = (const float*)d_in[3];
    const float* bl = (const float*)d_in[4];
    const float* ga = (const float*)d_in[5];
    const float* be = (const float*)d_in[6];
    float* out = (float*)d_out;

    prep_transpose_kernel<<<1024, 256>>>(Wd, Wl);

    const int smem_bytes = SMEM_FLOATS * (int)sizeof(float);   // 182272 B
    cudaFuncSetAttribute(scalarizer_kernel,
                         cudaFuncAttributeMaxDynamicSharedMemorySize, smem_bytes);
    scalarizer_kernel<<<4096, 256, smem_bytes>>>(v, We, bl, ga, be, out);
}

// round 12
// speedup vs baseline: 1.5626x; 1.5626x over previous
#include <cuda_runtime.h>
#include <cuda_bf16.h>
#include <cstdint>
#include <cstddef>

// ---------------------------------------------------------------------------
// Scalarizer — HMMA (mma.sync bf16) split-precision version.
// tcgen05 is rejected by this toolchain (.target sm_103), so both GEMMs run on
// tensor cores via mma.sync.m16n8k16 bf16 with a 2-term hi/lo split
// (3 MMAs per k-step => ~2^-17 element error, fp32 accumulate).
// Middle section + LayerNorm + exact GELU stay in fp32 CUDA cores.
// ---------------------------------------------------------------------------

// Pre-split weights (bf16 hi/lo), built by prep kernel each launch.
static __device__ __nv_bfloat16 g_B1h[128 * 512], g_B1l[128 * 512];    // Wd  n x k
static __device__ __nv_bfloat16 g_B2h[512 * 512], g_B2l[512 * 512];    // Wl  n x k

// ----------------------------- helpers --------------------------------------
__device__ __forceinline__ uint32_t smem_u32(const void* p) {
    uint32_t a;
    asm("{ .reg .u64 t; cvta.to.shared.u64 t, %1; cvt.u32.u64 %0, t; }" : "=r"(a) : "l"(p));
    return a;
}
__device__ __forceinline__ void ldsm4(uint32_t a, uint32_t r[4]) {
    asm volatile("ldmatrix.sync.aligned.m8n8.x4.shared.b16 {%0,%1,%2,%3}, [%4];"
                 : "=r"(r[0]), "=r"(r[1]), "=r"(r[2]), "=r"(r[3]) : "r"(a));
}
__device__ __forceinline__ void ldsm2(uint32_t a, uint32_t r[2]) {
    asm volatile("ldmatrix.sync.aligned.m8n8.x2.shared.b16 {%0,%1}, [%2];"
                 : "=r"(r[0]), "=r"(r[1]) : "r"(a));
}
__device__ __forceinline__ void mma16816(float c[4], const uint32_t a[4],
                                         uint32_t b0, uint32_t b1) {
    asm volatile("mma.sync.aligned.m16n8k16.row.col.f32.bf16.bf16.f32 "
                 "{%0,%1,%2,%3}, {%4,%5,%6,%7}, {%8,%9}, {%0,%1,%2,%3};"
                 : "+f"(c[0]), "+f"(c[1]), "+f"(c[2]), "+f"(c[3])
                 : "r"(a[0]), "r"(a[1]), "r"(a[2]), "r"(a[3]), "r"(b0), "r"(b1));
}
// bf16 2-term split of a float4, packed as 2x uint2 (4 bf16 each).
__device__ __forceinline__ void split_pack(float4 q, uint2& hi, uint2& lo) {
    float f[4] = {q.x, q.y, q.z, q.w};
    unsigned short h[4], l[4];
#pragma unroll
    for (int i = 0; i < 4; i++) {
        __nv_bfloat16 hb = __float2bfloat16(f[i]);
        __nv_bfloat16 lb = __float2bfloat16(f[i] - __bfloat162float(hb));
        h[i] = __bfloat16_as_ushort(hb);
        l[i] = __bfloat16_as_ushort(lb);
    }
    hi.x = (uint32_t)h[0] | ((uint32_t)h[1] << 16);
    hi.y = (uint32_t)h[2] | ((uint32_t)h[3] << 16);
    lo.x = (uint32_t)l[0] | ((uint32_t)l[1] << 16);
    lo.y = (uint32_t)l[2] | ((uint32_t)l[3] << 16);
}

// --------------------------- prep: split weights -----------------------------
__global__ void prep_weights(const float* __restrict__ Wd, const float* __restrict__ Wl) {
    int i = blockIdx.x * blockDim.x + threadIdx.x;
    if (i < 65536) {
        float x = Wd[i];
        __nv_bfloat16 h = __float2bfloat16(x);
        g_B1h[i] = h;
        g_B1l[i] = __float2bfloat16(x - __bfloat162float(h));
    }
    if (i < 262144) {
        float x = Wl[i];
        __nv_bfloat16 h = __float2bfloat16(x);
        g_B2h[i] = h;
        g_B2l[i] = __float2bfloat16(x - __bfloat162float(h));
    }
}

// ------------------------------- main kernel --------------------------------
// SMEM byte offsets (all 16B aligned):
//   phase1 tiles: A1h 0 (96x72 bf16, pitch 144B), A1l 13824, B1h 27648 (128x72),
//                 B1l 46080 .. 64512
//   sVred  fp32 96x132 at 0 (reuses dead tiles)          .. 50688
//   sV2    fp32 32x516 at 81920                          .. 147968
//   A2h/A2l bf16 32x520 (pitch 1040B) at 0 / 33280       .. 66560
//   B2h/B2l bf16 512x72 (pitch 144B) at 66560 / 140288   .. 214016
//   sParams (bias|gamma|beta, 1536 f) at 214016          .. 220160
//   sRed 256 f at 220160                                 .. 221184
static constexpr int OFF_A1H = 0,     OFF_A1L = 13824;
static constexpr int OFF_B1H = 27648, OFF_B1L = 46080;
static constexpr int OFF_SV2 = 81920;
static constexpr int OFF_A2H = 0,     OFF_A2L = 33280;
static constexpr int OFF_B2H = 66560, OFF_B2L = 140288;
static constexpr int OFF_PAR = 214016, OFF_RED = 220160;
static constexpr int SMEM_BYTES = 221184;

__global__ void __launch_bounds__(256, 1)
scalarizer_mma(const float* __restrict__ v,
               const float* __restrict__ W_emb,
               const float* __restrict__ b_lin,
               const float* __restrict__ gamma,
               const float* __restrict__ beta,
               float* __restrict__ out) {
    extern __shared__ char sm[];
    const int tid = threadIdx.x, lane = tid & 31, warp = tid >> 5;
    const uint32_t su = smem_u32(sm);
    float* sPar = (float*)(sm + OFF_PAR);
    float* sRed = (float*)(sm + OFF_RED);
    for (int i = tid; i < 512; i += 256) {
        sPar[i]        = b_lin[i];
        sPar[512 + i]  = gamma[i];
        sPar[1024 + i] = beta[i];
    }
    const float* slab = v + (size_t)blockIdx.x * (32 * 3 * 512);   // 96 x 512

    // ================= Phase 1: GEMM1 (96x512)@(512x128)^T =================
    // warp-tiles: mt 0..5 (m16), nt = warp + j*8 (n8), j=0..1
    float acc1[6][2][4];
#pragma unroll
    for (int mt = 0; mt < 6; mt++)
#pragma unroll
        for (int j = 0; j < 2; j++)
#pragma unroll
            for (int c = 0; c < 4; c++) acc1[mt][j][c] = 0.f;

    for (int kc = 0; kc < 8; kc++) {       // K chunks of 64
        __syncthreads();
        // stage A: v fp32 -> bf16 hi/lo, pitch 144B
        for (int i = tid; i < 1536; i += 256) {
            int m = i >> 4, c4 = i & 15;
            float4 q = *(const float4*)(slab + m * 512 + kc * 64 + c4 * 4);
            uint2 hi, lo; split_pack(q, hi, lo);
            *(uint2*)(sm + OFF_A1H + m * 144 + c4 * 8) = hi;
            *(uint2*)(sm + OFF_A1L + m * 144 + c4 * 8) = lo;
        }
        // stage B1 hi+lo (pre-split bf16): 16B copies
        for (int i = tid; i < 2048; i += 256) {
            int sel = i >> 10, j = i & 1023, r = j >> 3, c = j & 7;
            const uint4* src = (const uint4*)(sel ? (const void*)g_B1l : (const void*)g_B1h);
            *(uint4*)(sm + (sel ? OFF_B1L : OFF_B1H) + r * 144 + c * 16) =
                src[r * 64 + kc * 8 + c];
        }
        __syncthreads();
#pragma unroll
        for (int ks = 0; ks < 4; ks++) {
            uint32_t bh[2][2], bl[2][2];
#pragma unroll
            for (int j = 0; j < 2; j++) {
                int nt = warp + j * 8;
                uint32_t boff = (uint32_t)((nt * 8 + (lane & 7)) * 144 + ks * 32
                                           + ((lane >> 3) & 1) * 16);
                ldsm2(su + OFF_B1H + boff, bh[j]);
                ldsm2(su + OFF_B1L + boff, bl[j]);
            }
#pragma unroll
            for (int mt = 0; mt < 6; mt++) {
                uint32_t aoff = (uint32_t)((mt * 16 + (lane & 15)) * 144 + ks * 32
                                           + (lane >> 4) * 16);
                uint32_t ah[4], al[4];
                ldsm4(su + OFF_A1H + aoff, ah);
                ldsm4(su + OFF_A1L + aoff, al);
#pragma unroll
                for (int j = 0; j < 2; j++) {
                    mma16816(acc1[mt][j], ah, bh[j][0], bh[j][1]);
                    mma16816(acc1[mt][j], ah, bl[j][0], bl[j][1]);
                    mma16816(acc1[mt][j], al, bh[j][0], bh[j][1]);
                }
            }
        }
    }
    __syncthreads();
    // scatter accumulators -> sVred (fp32, pitch 132)
    float* sVred = (float*)sm;
#pragma unroll
    for (int mt = 0; mt < 6; mt++)
#pragma unroll
        for (int j = 0; j < 2; j++) {
            int nt  = warp + j * 8;
            int row = mt * 16 + (lane >> 2);
            int col = nt * 8 + (lane & 3) * 2;
            float2 a = make_float2(acc1[mt][j][0], acc1[mt][j][1]);
            float2 b = make_float2(acc1[mt][j][2], acc1[mt][j][3]);
            *(float2*)(sVred + row * 132 + col)       = a;
            *(float2*)(sVred + (row + 8) * 132 + col) = b;
        }
    __syncthreads();

    // ================= Phase 2: middle section (fp32, warp/sample) ==========
    float* sV2 = (float*)(sm + OFF_SV2);   // 32 x 516
    {
        float weA[3][4];
#pragma unroll
        for (int e = 0; e < 3; e++) {
            float4 q = *(const float4*)(W_emb + e * 128 + lane * 4);
            weA[e][0] = q.x; weA[e][1] = q.y; weA[e][2] = q.z; weA[e][3] = q.w;
        }
        for (int s = warp; s < 32; s += 8) {
            float vrA[3][4];
#pragma unroll
            for (int i = 0; i < 3; i++) {
                float4 q = *(const float4*)(sVred + (3 * s + i) * 132 + lane * 4);
                vrA[i][0] = q.x; vrA[i][1] = q.y; vrA[i][2] = q.z; vrA[i][3] = q.w;
            }
            float p[3][3];
#pragma unroll
            for (int i = 0; i < 3; i++)
#pragma unroll
                for (int e = 0; e < 3; e++) {
                    float sv = vrA[i][0] * weA[e][0] + vrA[i][1] * weA[e][1]
                             + vrA[i][2] * weA[e][2] + vrA[i][3] * weA[e][3];
                    for (int off = 16; off; off >>= 1)
                        sv += __shfl_xor_sync(0xffffffffu, sv, off);
                    p[i][e] = sv;
                }
            float nd[3][3];
#pragma unroll
            for (int e = 0; e < 3; e++) {
                float dn = sqrtf(p[0][e]*p[0][e] + p[1][e]*p[1][e] + p[2][e]*p[2][e]);
                float inv = 1.0f / (dn + 1e-3f);
                nd[0][e] = p[0][e]*inv; nd[1][e] = p[1][e]*inv; nd[2][e] = p[2][e]*inv;
            }
            float nrmA[4], prA[3][4];
#pragma unroll
            for (int c = 0; c < 4; c++) {
                float v0 = vrA[0][c], v1 = vrA[1][c], v2c = vrA[2][c];
                float nn = sqrtf(v0*v0 + v1*v1 + v2c*v2c);
                nrmA[c] = nn;
                float inv = 1.0f / (nn + 1e-3f);
                float nv0 = v0*inv, nv1 = v1*inv, nv2 = v2c*inv;
#pragma unroll
                for (int e = 0; e < 3; e++)
                    prA[e][c] = nv0*nd[0][e] + nv1*nd[1][e] + nv2*nd[2][e];
            }
            float* dst = sV2 + s * 516;
            *(float4*)(dst + lane * 4) = make_float4(nrmA[0], nrmA[1], nrmA[2], nrmA[3]);
#pragma unroll
            for (int e = 0; e < 3; e++)
                *(float4*)(dst + 128 + e * 128 + lane * 4) =
                    make_float4(prA[e][0], prA[e][1], prA[e][2], prA[e][3]);
        }
    }
    __syncthreads();

    // convert v2 fp32 -> A2 bf16 hi/lo (pitch 1040B), full K resident
    for (int i = tid; i < 4096; i += 256) {
        int r = i >> 7, c4 = i & 127;
        float4 q = *(const float4*)(sV2 + r * 516 + c4 * 4);
        uint2 hi, lo; split_pack(q, hi, lo);
        *(uint2*)(sm + OFF_A2H + r * 1040 + c4 * 8) = hi;
        *(uint2*)(sm + OFF_A2L + r * 1040 + c4 * 8) = lo;
    }

    // ================= Phase 3: GEMM2 (32x512)@(512x512)^T ==================
    // warp-tiles: mt2 = warp>>2 (m16), nts (warp&3)*16 .. +15 (n8), paired x4
    float acc2[8][2][4];
#pragma unroll
    for (int np = 0; np < 8; np++)
#pragma unroll
        for (int j = 0; j < 2; j++)
#pragma unroll
            for (int c = 0; c < 4; c++) acc2[np][j][c] = 0.f;

    const int mt2 = warp >> 2, ntb = (warp & 3) * 16;

    for (int kc = 0; kc < 8; kc++) {
        __syncthreads();
        // stage B2 hi+lo chunk (512 rows x 64 k bf16), pitch 144B
        for (int i = tid; i < 8192; i += 256) {
            int sel = i >> 12, j = i & 4095, r = j >> 3, c = j & 7;
            const uint4* src = (const uint4*)(sel ? (const void*)g_B2l : (const void*)g_B2h);
            *(uint4*)(sm + (sel ? OFF_B2L : OFF_B2H) + r * 144 + c * 16) =
                src[r * 64 + kc * 8 + c];
        }
        __syncthreads();
#pragma unroll
        for (int ks = 0; ks < 4; ks++) {
            uint32_t aoff = (uint32_t)((mt2 * 16 + (lane & 15)) * 1040
                                       + kc * 128 + ks * 32 + (lane >> 4) * 16);
            uint32_t ah[4], al[4];
            ldsm4(su + OFF_A2H + aoff, ah);
            ldsm4(su + OFF_A2L + aoff, al);
#pragma unroll
            for (int np = 0; np < 8; np++) {
                int nt0 = ntb + np * 2;
                uint32_t boff = (uint32_t)((nt0 * 8 + (lane & 15)) * 144
                                           + ks * 32 + (lane >> 4) * 16);
                uint32_t bh[4], bl[4];
                ldsm4(su + OFF_B2H + boff, bh);
                ldsm4(su + OFF_B2L + boff, bl);
                mma16816(acc2[np][0], ah, bh[0], bh[2]);
                mma16816(acc2[np][0], ah, bl[0], bl[2]);
                mma16816(acc2[np][0], al, bh[0], bh[2]);
                mma16816(acc2[np][1], ah, bh[1], bh[3]);
                mma16816(acc2[np][1], ah, bl[1], bl[3]);
                mma16816(acc2[np][1], al, bh[1], bh[3]);
            }
        }
    }

    // ================= Epilogue: bias + LayerNorm + exact GELU ==============
    const int rlo = mt2 * 16 + (lane >> 2), rhi = rlo + 8;
    float slo = 0.f, sslo = 0.f, shi = 0.f, sshi = 0.f;
#pragma unroll
    for (int np = 0; np < 8; np++)
#pragma unroll
        for (int j = 0; j < 2; j++) {
            int col = (ntb + np * 2 + j) * 8 + (lane & 3) * 2;
            float2 bb = *(const float2*)(sPar + col);
            acc2[np][j][0] += bb.x; acc2[np][j][1] += bb.y;
            acc2[np][j][2] += bb.x; acc2[np][j][3] += bb.y;
            slo += acc2[np][j][0] + acc2[np][j][1];
            sslo += acc2[np][j][0]*acc2[np][j][0] + acc2[np][j][1]*acc2[np][j][1];
            shi += acc2[np][j][2] + acc2[np][j][3];
            sshi += acc2[np][j][2]*acc2[np][j][2] + acc2[np][j][3]*acc2[np][j][3];
        }
#pragma unroll
    for (int off = 1; off <= 2; off <<= 1) {
        slo  += __shfl_xor_sync(0xffffffffu, slo,  off);
        sslo += __shfl_xor_sync(0xffffffffu, sslo, off);
        shi  += __shfl_xor_sync(0xffffffffu, shi,  off);
        sshi += __shfl_xor_sync(0xffffffffu, sshi, off);
    }
    int wq = warp & 3;
    if ((lane & 3) == 0) {
        sRed[rlo * 8 + wq * 2 + 0] = slo;
        sRed[rlo * 8 + wq * 2 + 1] = sslo;
        sRed[rhi * 8 + wq * 2 + 0] = shi;
        sRed[rhi * 8 + wq * 2 + 1] = sshi;
    }
    __syncthreads();
    float Sl = 0.f, SSl = 0.f, Sh = 0.f, SSh = 0.f;
#pragma unroll
    for (int w = 0; w < 4; w++) {
        Sl  += sRed[rlo * 8 + w * 2 + 0];
        SSl += sRed[rlo * 8 + w * 2 + 1];
        Sh  += sRed[rhi * 8 + w * 2 + 0];
        SSh += sRed[rhi * 8 + w * 2 + 1];
    }
    float mu_lo = Sl * (1.f/512.f), var_lo = SSl * (1.f/512.f) - mu_lo*mu_lo;
    float mu_hi = Sh * (1.f/512.f), var_hi = SSh * (1.f/512.f) - mu_hi*mu_hi;
    float rs_lo = rsqrtf(var_lo + 1e-5f), rs_hi = rsqrtf(var_hi + 1e-5f);

    float* obase = out + (size_t)blockIdx.x * 32 * 512;
#pragma unroll
    for (int np = 0; np < 8; np++)
#pragma unroll
        for (int j = 0; j < 2; j++) {
            int col = (ntb + np * 2 + j) * 8 + (lane & 3) * 2;
            float2 g2 = *(const float2*)(sPar + 512 + col);
            float2 b2 = *(const float2*)(sPar + 1024 + col);
            float y0 = (acc2[np][j][0] - mu_lo) * rs_lo * g2.x + b2.x;
            float y1 = (acc2[np][j][1] - mu_lo) * rs_lo * g2.y + b2.y;
            float y2 = (acc2[np][j][2] - mu_hi) * rs_hi * g2.x + b2.x;
            float y3 = (acc2[np][j][3] - mu_hi) * rs_hi * g2.y + b2.y;
            const float k = 0.70710678118654752f;
            y0 = 0.5f * y0 * (1.0f + erff(y0 * k));
            y1 = 0.5f * y1 * (1.0f + erff(y1 * k));
            y2 = 0.5f * y2 * (1.0f + erff(y2 * k));
            y3 = 0.5f * y3 * (1.0f + erff(y3 * k));
            *(float2*)(obase + (size_t)rlo * 512 + col) = make_float2(y0, y1);
            *(float2*)(obase + (size_t)rhi * 512 + col) = make_float2(y2, y3);
        }
}

// ------------------------------- launch --------------------------------------
extern "C" void kernel_launch(void* const* d_in, const int* in_sizes, int n_in,
                              void* d_out, int out_size) {
    (void)in_sizes; (void)n_in; (void)out_size;
    const float* v  = (const float*)d_in[0];
    const float* Wd = (const float*)d_in[1];
    const float* We = (const float*)d_in[2];
    const float* Wl = (const float*)d_in[3];
    const float* bl = (const float*)d_in[4];
    const float* ga = (const float*)d_in[5];
    const float* be = (const float*)d_in[6];
    float* out = (float*)d_out;

    prep_weights<<<1024, 256>>>(Wd, Wl);

    cudaFuncSetAttribute(scalarizer_mma,
                         cudaFuncAttributeMaxDynamicSharedMemorySize, SMEM_BYTES);
    scalarizer_mma<<<4096, 256, SMEM_BYTES>>>(v, We, bl, ga, be, out);
}